// round 9
// baseline (speedup 1.0000x reference)
#include <cuda_runtime.h>
#include <cuda_bf16.h>
#include <cuda_fp16.h>
#include <cstdint>

#define NN   4096
#define FF   512
#define UU   64
#define HH   8
#define HU   (HH*UU)     // 512
#define LRELU 0.2f
#define EMAX 256         // max edges/row (mean 42, 33-sigma safe; writes clamped)

// ---------------- scratch ----------------
__device__ __half g_hfeat[NN * HU];           // [N, H*U] fp16, 4 MB (L2-resident)
__device__ float g_fs[NN * HH];
__device__ float g_fn[NN * HH];
__device__ __nv_bfloat16 g_Xhi[NN * FF];
__device__ __nv_bfloat16 g_Xlo[NN * FF];
__device__ __nv_bfloat16 g_Whi[HU * FF];      // W^T [c][k]
__device__ __nv_bfloat16 g_Wlo[HU * FF];

// ---------------- helpers ----------------
__device__ __forceinline__ uint32_t smem_u32(const void* p) {
    uint32_t a;
    asm("{ .reg .u64 t; cvta.to.shared.u64 t, %1; cvt.u32.u64 %0, t; }" : "=r"(a) : "l"(p));
    return a;
}
__device__ __forceinline__ void ldsm_x4(uint32_t* r, uint32_t addr) {
    asm volatile("ldmatrix.sync.aligned.m8n8.x4.shared.b16 {%0,%1,%2,%3}, [%4];"
        : "=r"(r[0]), "=r"(r[1]), "=r"(r[2]), "=r"(r[3]) : "r"(addr));
}
__device__ __forceinline__ void mma16816(float* c, const uint32_t* a, const uint32_t* b) {
    asm volatile("mma.sync.aligned.m16n8k16.row.col.f32.bf16.bf16.f32 "
        "{%0,%1,%2,%3}, {%4,%5,%6,%7}, {%8,%9}, {%0,%1,%2,%3};"
        : "+f"(c[0]), "+f"(c[1]), "+f"(c[2]), "+f"(c[3])
        : "r"(a[0]), "r"(a[1]), "r"(a[2]), "r"(a[3]), "r"(b[0]), "r"(b[1]));
}
__device__ __forceinline__ void cp16(uint32_t dst, const void* src) {
    asm volatile("cp.async.cg.shared.global [%0], [%1], 16;" :: "r"(dst), "l"(src));
}
#define CP_COMMIT() asm volatile("cp.async.commit_group;" ::: "memory")
#define CP_WAIT1()  asm volatile("cp.async.wait_group 1;" ::: "memory")
#define CP_WAIT0()  asm volatile("cp.async.wait_group 0;" ::: "memory")

// ---------------- preprocess: split X into bf16 hi/lo ----------------
__global__ __launch_bounds__(256)
void split_X_k(const float* __restrict__ X)
{
    int idx = blockIdx.x * 256 + threadIdx.x;
    float4 v = reinterpret_cast<const float4*>(X)[idx];
    __nv_bfloat16 h0 = __float2bfloat16(v.x), h1 = __float2bfloat16(v.y);
    __nv_bfloat16 h2 = __float2bfloat16(v.z), h3 = __float2bfloat16(v.w);
    __nv_bfloat16 l0 = __float2bfloat16(v.x - __bfloat162float(h0));
    __nv_bfloat16 l1 = __float2bfloat16(v.y - __bfloat162float(h1));
    __nv_bfloat16 l2 = __float2bfloat16(v.z - __bfloat162float(h2));
    __nv_bfloat16 l3 = __float2bfloat16(v.w - __bfloat162float(h3));
    __nv_bfloat162* ph = reinterpret_cast<__nv_bfloat162*>(g_Xhi);
    __nv_bfloat162* pl = reinterpret_cast<__nv_bfloat162*>(g_Xlo);
    ph[idx * 2]     = __halves2bfloat162(h0, h1);
    ph[idx * 2 + 1] = __halves2bfloat162(h2, h3);
    pl[idx * 2]     = __halves2bfloat162(l0, l1);
    pl[idx * 2 + 1] = __halves2bfloat162(l2, l3);
}

// ---------------- preprocess: W [H,F,U] -> W^T bf16 hi/lo [c][k] ----------------
__global__ __launch_bounds__(256)
void split_W_k(const float* __restrict__ W)
{
    __shared__ float t[32][33];
    const int k0 = blockIdx.x * 32;
    const int c0 = blockIdx.y * 32;
    const int h  = c0 >> 6;
    const int ub = c0 & 63;
    const int tx = threadIdx.x & 31, ty = threadIdx.x >> 5;

    for (int kk = ty; kk < 32; kk += 8)
        t[kk][tx] = W[(size_t)h * FF * UU + (size_t)(k0 + kk) * UU + ub + tx];
    __syncthreads();
    for (int cc = ty; cc < 32; cc += 8) {
        float v = t[tx][cc];
        __nv_bfloat16 hi = __float2bfloat16(v);
        g_Whi[(size_t)(c0 + cc) * FF + k0 + tx] = hi;
        g_Wlo[(size_t)(c0 + cc) * FF + k0 + tx] = __float2bfloat16(v - __bfloat162float(hi));
    }
}

// ---------------- Kernel 1: bf16x3 GEMM + fused f_self/f_neigh ----------------
#define KCHUNK   32
#define ROWB     80
#define A_BYTES  (128 * ROWB)
#define B_BYTES  (64 * ROWB)
#define STAGE_B  (2 * A_BYTES + 2 * B_BYTES)
#define GEMM_SMEM (2 * STAGE_B)

__global__ __launch_bounds__(256)
void gat_gemm_mma(const float* __restrict__ a_self, const float* __restrict__ a_neigh)
{
    extern __shared__ __align__(16) char dyn[];
    __shared__ float sm_as[UU], sm_an[UU];
    __shared__ float sred_fs[128], sred_fn[128];

    const int tid  = threadIdx.x;
    const int lane = tid & 31, wid = tid >> 5;
    const int bm = blockIdx.x * 128;
    const int hb = blockIdx.y;
    const int bn = hb * 64;
    const int mw = (wid >> 1) * 32;
    const int nw = (wid & 1) * 32;

    if (tid < UU) {
        sm_as[tid] = a_self[hb * UU + tid];
        sm_an[tid] = a_neigh[hb * UU + tid];
    }

    const uint32_t sbase = smem_u32(dyn);

    float acc[2][4][4];
#pragma unroll
    for (int mi = 0; mi < 2; mi++)
#pragma unroll
        for (int nj = 0; nj < 4; nj++)
#pragma unroll
            for (int q = 0; q < 4; q++) acc[mi][nj][q] = 0.f;

    const int a_row0 = tid >> 2, a_seg = tid & 3;
    const int b_row  = tid >> 2, b_seg = tid & 3;
    const int a_r = (lane & 15);
    const int a_k = (lane >> 4) * 8;
    const int b_c = ((lane >> 4) << 3) + (lane & 7);
    const int b_k = ((lane >> 3) & 1) * 8;

    auto issue = [&](int t) {
        const int st = t & 1;
        const uint32_t pAh = sbase + st * STAGE_B;
        const uint32_t pAl = pAh + A_BYTES;
        const uint32_t pBh = pAl + A_BYTES;
        const uint32_t pBl = pBh + B_BYTES;
        const int kc = t * KCHUNK;
#pragma unroll
        for (int it = 0; it < 2; it++) {
            int row = a_row0 + it * 64;
            size_t go = (size_t)(bm + row) * FF + kc + a_seg * 8;
            uint32_t so = (uint32_t)(row * ROWB + a_seg * 16);
            cp16(pAh + so, g_Xhi + go);
            cp16(pAl + so, g_Xlo + go);
        }
        {
            size_t go = (size_t)(bn + b_row) * FF + kc + b_seg * 8;
            uint32_t so = (uint32_t)(b_row * ROWB + b_seg * 16);
            cp16(pBh + so, g_Whi + go);
            cp16(pBl + so, g_Wlo + go);
        }
        CP_COMMIT();
    };

    issue(0);
    const int T = FF / KCHUNK;
    for (int t = 0; t < T; t++) {
        if (t + 1 < T) { issue(t + 1); CP_WAIT1(); }
        else           { CP_WAIT0(); }
        __syncthreads();

        const int st = t & 1;
        const uint32_t pAh = sbase + st * STAGE_B;
        const uint32_t pAl = pAh + A_BYTES;
        const uint32_t pBh = pAl + A_BYTES;
        const uint32_t pBl = pBh + B_BYTES;

#pragma unroll
        for (int ks = 0; ks < 2; ks++) {
            const int kk = ks * 16;
            uint32_t ah[2][4], al[2][4];
#pragma unroll
            for (int mi = 0; mi < 2; mi++) {
                uint32_t ao = (uint32_t)((mw + mi * 16 + a_r) * ROWB + (kk + a_k) * 2);
                ldsm_x4(ah[mi], pAh + ao);
                ldsm_x4(al[mi], pAl + ao);
            }
            uint32_t bh[4][2], bl[4][2];
#pragma unroll
            for (int bj = 0; bj < 2; bj++) {
                uint32_t bo = (uint32_t)((nw + bj * 16 + b_c) * ROWB + (kk + b_k) * 2);
                uint32_t r[4];
                ldsm_x4(r, pBh + bo);
                bh[bj * 2][0] = r[0]; bh[bj * 2][1] = r[1];
                bh[bj * 2 + 1][0] = r[2]; bh[bj * 2 + 1][1] = r[3];
                ldsm_x4(r, pBl + bo);
                bl[bj * 2][0] = r[0]; bl[bj * 2][1] = r[1];
                bl[bj * 2 + 1][0] = r[2]; bl[bj * 2 + 1][1] = r[3];
            }
#pragma unroll
            for (int mi = 0; mi < 2; mi++)
#pragma unroll
                for (int nj = 0; nj < 4; nj++) {
                    mma16816(acc[mi][nj], ah[mi], bh[nj]);
                    mma16816(acc[mi][nj], ah[mi], bl[nj]);
                    mma16816(acc[mi][nj], al[mi], bh[nj]);
                }
        }
        __syncthreads();
    }

    // ---- epilogue: store hfeat (fp16) + fused f_self/f_neigh ----
    const int er = lane >> 2;
    const int ec = (lane & 3) * 2;
#pragma unroll
    for (int mi = 0; mi < 2; mi++) {
        const int row = bm + mw + mi * 16 + er;
#pragma unroll
        for (int nj = 0; nj < 4; nj++) {
            const int col = bn + nw + nj * 8 + ec;
            *reinterpret_cast<__half2*>(g_hfeat + (size_t)row * HU + col) =
                __floats2half2_rn(acc[mi][nj][0], acc[mi][nj][1]);
            *reinterpret_cast<__half2*>(g_hfeat + (size_t)(row + 8) * HU + col) =
                __floats2half2_rn(acc[mi][nj][2], acc[mi][nj][3]);
        }
    }

    float fsv[2][2], fnv[2][2];
#pragma unroll
    for (int mi = 0; mi < 2; mi++) {
        float fs0 = 0.f, fs1 = 0.f, fn0 = 0.f, fn1 = 0.f;
#pragma unroll
        for (int nj = 0; nj < 4; nj++) {
            const int c = nw + nj * 8 + ec;
            float as0 = sm_as[c], as1 = sm_as[c + 1];
            float an0 = sm_an[c], an1 = sm_an[c + 1];
            fs0 += acc[mi][nj][0] * as0 + acc[mi][nj][1] * as1;
            fs1 += acc[mi][nj][2] * as0 + acc[mi][nj][3] * as1;
            fn0 += acc[mi][nj][0] * an0 + acc[mi][nj][1] * an1;
            fn1 += acc[mi][nj][2] * an0 + acc[mi][nj][3] * an1;
        }
        fsv[mi][0] = fs0; fsv[mi][1] = fs1;
        fnv[mi][0] = fn0; fnv[mi][1] = fn1;
    }
#pragma unroll
    for (int mi = 0; mi < 2; mi++)
#pragma unroll
        for (int rh = 0; rh < 2; rh++) {
            fsv[mi][rh] += __shfl_xor_sync(0xFFFFFFFFu, fsv[mi][rh], 1);
            fsv[mi][rh] += __shfl_xor_sync(0xFFFFFFFFu, fsv[mi][rh], 2);
            fnv[mi][rh] += __shfl_xor_sync(0xFFFFFFFFu, fnv[mi][rh], 1);
            fnv[mi][rh] += __shfl_xor_sync(0xFFFFFFFFu, fnv[mi][rh], 2);
        }
    if (nw == 0 && (lane & 3) == 0) {
#pragma unroll
        for (int mi = 0; mi < 2; mi++) {
            sred_fs[mw + mi * 16 + er]     = fsv[mi][0];
            sred_fs[mw + mi * 16 + er + 8] = fsv[mi][1];
            sred_fn[mw + mi * 16 + er]     = fnv[mi][0];
            sred_fn[mw + mi * 16 + er + 8] = fnv[mi][1];
        }
    }
    __syncthreads();
    if (nw == 32 && (lane & 3) == 0) {
#pragma unroll
        for (int mi = 0; mi < 2; mi++)
#pragma unroll
            for (int rh = 0; rh < 2; rh++) {
                const int r = mw + mi * 16 + er + rh * 8;
                g_fs[(size_t)(bm + r) * HH + hb] = sred_fs[r] + fsv[mi][rh];
                g_fn[(size_t)(bm + r) * HH + hb] = sred_fn[r] + fnv[mi][rh];
            }
    }
}

// ---------------- Kernel 3: aggregation (uint4 gather, 2-way edge parallel) ----------------
__global__ __launch_bounds__(128)
void gat_aggregate(const float* __restrict__ A,
                   const float* __restrict__ bias,
                   float* __restrict__ out)
{
    const int i    = blockIdx.x;
    const int tid  = threadIdx.x;           // 0..127
    const int lane = tid & 31, wid = tid >> 5;
    const int eh   = tid >> 6;              // edge-parity half (0/1)
    const int u    = tid & 63;              // column octet: cols [u*8, u*8+8)
    const int myh  = u >> 3;                // head of this thread's columns

    __shared__ int   sm_edges[EMAX];        // stores j<<9 (half-unit row offset)
    __shared__ float sm_w[HH][EMAX];
    __shared__ int   sm_psum[4];
    __shared__ float sm_fs[HH], sm_den[HH];
    __shared__ float sm_part[HU];           // cross-half partial sums (2 KB)

    if (tid < HH) sm_fs[tid] = g_fs[i * HH + tid];

    // ---- pass 1: count nonzeros in this thread's 32 columns ----
    const float4* Arow = reinterpret_cast<const float4*>(A + (size_t)i * NN);
    int cnt = 0;
#pragma unroll
    for (int q = 0; q < 8; q++) {
        float4 v = Arow[tid * 8 + q];
        cnt += (v.x != 0.f) + (v.y != 0.f) + (v.z != 0.f) + (v.w != 0.f);
    }
    int incl = cnt;
#pragma unroll
    for (int o = 1; o < 32; o <<= 1) {
        int nv = __shfl_up_sync(0xFFFFFFFFu, incl, o);
        if (lane >= o) incl += nv;
    }
    if (lane == 31) sm_psum[wid] = incl;
    __syncthreads();
    if (tid == 0) {
        int s = 0;
#pragma unroll
        for (int w = 0; w < 4; w++) { int v = sm_psum[w]; sm_psum[w] = s + v; s += v; }
    }
    __syncthreads();
    // ---- pass 2: rescan (L1-hot) and append ordered (clamped) ----
    {
        int base = (wid ? sm_psum[wid - 1] : 0) + incl - cnt;
        int col0 = tid * 32;
#pragma unroll
        for (int q = 0; q < 8; q++) {
            float4 v = Arow[tid * 8 + q];
            int c = col0 + q * 4;
            if (v.x != 0.f) { sm_edges[min(base, EMAX - 1)] = (c + 0) << 9; base++; }
            if (v.y != 0.f) { sm_edges[min(base, EMAX - 1)] = (c + 1) << 9; base++; }
            if (v.z != 0.f) { sm_edges[min(base, EMAX - 1)] = (c + 2) << 9; base++; }
            if (v.w != 0.f) { sm_edges[min(base, EMAX - 1)] = (c + 3) << 9; base++; }
        }
    }
    __syncthreads();
    const int E = min(sm_psum[3], EMAX);

    // ---- weight phase: all E edges, all 8 heads, one pass ----
    for (int e = tid; e < E; e += 128) {
        int j8 = sm_edges[e] >> 6;          // j*8
        float4 f0 = *reinterpret_cast<const float4*>(g_fn + j8);
        float4 f1 = *reinterpret_cast<const float4*>(g_fn + j8 + 4);
        float fn8[8] = {f0.x, f0.y, f0.z, f0.w, f1.x, f1.y, f1.z, f1.w};
#pragma unroll
        for (int hh = 0; hh < HH; hh++) {
            float x = sm_fs[hh] + fn8[hh];
            x = x > 0.f ? x : LRELU * x;
            sm_w[hh][e] = __expf(x);
        }
    }
    __syncthreads();

    // ---- den partials (16 threads per head hden) ----
    {
        const int hden = tid >> 4, sub = tid & 15;
        float den = 0.f;
        for (int e = sub; e < E; e += 16) den += sm_w[hden][e];
#pragma unroll
        for (int o = 8; o; o >>= 1) den += __shfl_xor_sync(0xFFFFFFFFu, den, o);
        if (sub == 0) sm_den[hden] = den;
    }

    // ---- gather-FMA: uint4 loads, halves process even/odd edges ----
    const __half* hp = g_hfeat + u * 8;
    float acc[8];
#pragma unroll
    for (int q = 0; q < 8; q++) acc[q] = 0.f;

    int e = eh;
    for (; e + 6 < E; e += 8) {             // 4 edges per thread per iter
        int o0 = sm_edges[e],     o1 = sm_edges[e + 2];
        int o2 = sm_edges[e + 4], o3 = sm_edges[e + 6];
        float w0 = sm_w[myh][e],     w1 = sm_w[myh][e + 2];
        float w2 = sm_w[myh][e + 4], w3 = sm_w[myh][e + 6];
        uint4 v0 = *reinterpret_cast<const uint4*>(hp + o0);
        uint4 v1 = *reinterpret_cast<const uint4*>(hp + o1);
        uint4 v2 = *reinterpret_cast<const uint4*>(hp + o2);
        uint4 v3 = *reinterpret_cast<const uint4*>(hp + o3);
#pragma unroll
        for (int q = 0; q < 4; q++) {
            float2 p0 = __half22float2(*reinterpret_cast<__half2*>(&(&v0.x)[q]));
            float2 p1 = __half22float2(*reinterpret_cast<__half2*>(&(&v1.x)[q]));
            float2 p2 = __half22float2(*reinterpret_cast<__half2*>(&(&v2.x)[q]));
            float2 p3 = __half22float2(*reinterpret_cast<__half2*>(&(&v3.x)[q]));
            acc[q * 2]     = fmaf(w0, p0.x, acc[q * 2]);
            acc[q * 2 + 1] = fmaf(w0, p0.y, acc[q * 2 + 1]);
            acc[q * 2]     = fmaf(w1, p1.x, acc[q * 2]);
            acc[q * 2 + 1] = fmaf(w1, p1.y, acc[q * 2 + 1]);
            acc[q * 2]     = fmaf(w2, p2.x, acc[q * 2]);
            acc[q * 2 + 1] = fmaf(w2, p2.y, acc[q * 2 + 1]);
            acc[q * 2]     = fmaf(w3, p3.x, acc[q * 2]);
            acc[q * 2 + 1] = fmaf(w3, p3.y, acc[q * 2 + 1]);
        }
    }
    for (; e < E; e += 2) {
        int o0 = sm_edges[e];
        float w0 = sm_w[myh][e];
        uint4 v0 = *reinterpret_cast<const uint4*>(hp + o0);
#pragma unroll
        for (int q = 0; q < 4; q++) {
            float2 p0 = __half22float2(*reinterpret_cast<__half2*>(&(&v0.x)[q]));
            acc[q * 2]     = fmaf(w0, p0.x, acc[q * 2]);
            acc[q * 2 + 1] = fmaf(w0, p0.y, acc[q * 2 + 1]);
        }
    }

    // ---- combine halves + finalize ----
    if (eh == 1) {
#pragma unroll
        for (int q = 0; q < 8; q++) sm_part[u * 8 + q] = acc[q];
    }
    __syncthreads();
    if (eh == 0) {
        const float rden = 1.f / sm_den[myh];
        float4 b0 = *reinterpret_cast<const float4*>(bias + u * 8);
        float4 b1 = *reinterpret_cast<const float4*>(bias + u * 8 + 4);
        float r[8];
#pragma unroll
        for (int q = 0; q < 8; q++) {
            float s = acc[q] + sm_part[u * 8 + q];
            r[q] = s * rden + (&b0.x)[q >= 4 ? 0 : 0], r[q] = 0.f; // placeholder overwritten below
        }
        r[0] = fmaf(acc[0] + sm_part[u * 8 + 0], rden, b0.x);
        r[1] = fmaf(acc[1] + sm_part[u * 8 + 1], rden, b0.y);
        r[2] = fmaf(acc[2] + sm_part[u * 8 + 2], rden, b0.z);
        r[3] = fmaf(acc[3] + sm_part[u * 8 + 3], rden, b0.w);
        r[4] = fmaf(acc[4] + sm_part[u * 8 + 4], rden, b1.x);
        r[5] = fmaf(acc[5] + sm_part[u * 8 + 5], rden, b1.y);
        r[6] = fmaf(acc[6] + sm_part[u * 8 + 6], rden, b1.z);
        r[7] = fmaf(acc[7] + sm_part[u * 8 + 7], rden, b1.w);
#pragma unroll
        for (int q = 0; q < 8; q++) r[q] = r[q] > 0.f ? r[q] : 0.f;
        float* op = out + (size_t)i * HU + u * 8;
        *reinterpret_cast<float4*>(op)     = make_float4(r[0], r[1], r[2], r[3]);
        *reinterpret_cast<float4*>(op + 4) = make_float4(r[4], r[5], r[6], r[7]);
    }
}

// ---------------- launch ----------------
extern "C" void kernel_launch(void* const* d_in, const int* in_sizes, int n_in,
                              void* d_out, int out_size)
{
    const float* X       = (const float*)d_in[0];
    const float* A       = (const float*)d_in[2];
    const float* W       = (const float*)d_in[3];
    const float* a_self  = (const float*)d_in[4];
    const float* a_neigh = (const float*)d_in[5];
    const float* bias    = (const float*)d_in[6];
    float* out = (float*)d_out;

    cudaFuncSetAttribute(gat_gemm_mma, cudaFuncAttributeMaxDynamicSharedMemorySize, GEMM_SMEM);

    split_X_k<<<NN * FF / 4 / 256, 256>>>(X);
    split_W_k<<<dim3(FF / 32, HU / 32), 256>>>(W);
    gat_gemm_mma<<<dim3(NN / 128, HU / 64), 256, GEMM_SMEM>>>(a_self, a_neigh);
    gat_aggregate<<<NN, 128>>>(A, bias, out);
}

// round 10
// speedup vs baseline: 1.0266x; 1.0266x over previous
#include <cuda_runtime.h>
#include <cuda_bf16.h>
#include <cuda_fp16.h>
#include <cstdint>

#define NN   4096
#define FF   512
#define UU   64
#define HH   8
#define HU   (HH*UU)     // 512
#define LRELU 0.2f
#define EMAX 256         // max edges/row (mean 42, 33-sigma safe; writes clamped)

// ---------------- scratch ----------------
__device__ __half g_hfeat[NN * HU];           // [N, H*U] fp16, 4 MB (L2-resident)
__device__ float g_fs[NN * HH];
__device__ float g_fn[NN * HH];
__device__ __nv_bfloat16 g_Xhi[NN * FF];
__device__ __nv_bfloat16 g_Xlo[NN * FF];
__device__ __nv_bfloat16 g_Whi[HU * FF];      // W^T [c][k]
__device__ __nv_bfloat16 g_Wlo[HU * FF];

// ---------------- helpers ----------------
__device__ __forceinline__ uint32_t smem_u32(const void* p) {
    uint32_t a;
    asm("{ .reg .u64 t; cvta.to.shared.u64 t, %1; cvt.u32.u64 %0, t; }" : "=r"(a) : "l"(p));
    return a;
}
__device__ __forceinline__ void ldsm_x4(uint32_t* r, uint32_t addr) {
    asm volatile("ldmatrix.sync.aligned.m8n8.x4.shared.b16 {%0,%1,%2,%3}, [%4];"
        : "=r"(r[0]), "=r"(r[1]), "=r"(r[2]), "=r"(r[3]) : "r"(addr));
}
__device__ __forceinline__ void mma16816(float* c, const uint32_t* a, const uint32_t* b) {
    asm volatile("mma.sync.aligned.m16n8k16.row.col.f32.bf16.bf16.f32 "
        "{%0,%1,%2,%3}, {%4,%5,%6,%7}, {%8,%9}, {%0,%1,%2,%3};"
        : "+f"(c[0]), "+f"(c[1]), "+f"(c[2]), "+f"(c[3])
        : "r"(a[0]), "r"(a[1]), "r"(a[2]), "r"(a[3]), "r"(b[0]), "r"(b[1]));
}
__device__ __forceinline__ void cp16(uint32_t dst, const void* src) {
    asm volatile("cp.async.cg.shared.global [%0], [%1], 16;" :: "r"(dst), "l"(src));
}
#define CP_COMMIT() asm volatile("cp.async.commit_group;" ::: "memory")
#define CP_WAIT1()  asm volatile("cp.async.wait_group 1;" ::: "memory")
#define CP_WAIT0()  asm volatile("cp.async.wait_group 0;" ::: "memory")

// ---------------- preprocess: split X into bf16 hi/lo ----------------
__global__ __launch_bounds__(256)
void split_X_k(const float* __restrict__ X)
{
    int idx = blockIdx.x * 256 + threadIdx.x;
    float4 v = reinterpret_cast<const float4*>(X)[idx];
    __nv_bfloat16 h0 = __float2bfloat16(v.x), h1 = __float2bfloat16(v.y);
    __nv_bfloat16 h2 = __float2bfloat16(v.z), h3 = __float2bfloat16(v.w);
    __nv_bfloat16 l0 = __float2bfloat16(v.x - __bfloat162float(h0));
    __nv_bfloat16 l1 = __float2bfloat16(v.y - __bfloat162float(h1));
    __nv_bfloat16 l2 = __float2bfloat16(v.z - __bfloat162float(h2));
    __nv_bfloat16 l3 = __float2bfloat16(v.w - __bfloat162float(h3));
    __nv_bfloat162* ph = reinterpret_cast<__nv_bfloat162*>(g_Xhi);
    __nv_bfloat162* pl = reinterpret_cast<__nv_bfloat162*>(g_Xlo);
    ph[idx * 2]     = __halves2bfloat162(h0, h1);
    ph[idx * 2 + 1] = __halves2bfloat162(h2, h3);
    pl[idx * 2]     = __halves2bfloat162(l0, l1);
    pl[idx * 2 + 1] = __halves2bfloat162(l2, l3);
}

// ---------------- preprocess: W [H,F,U] -> W^T bf16 hi/lo [c][k] ----------------
__global__ __launch_bounds__(256)
void split_W_k(const float* __restrict__ W)
{
    __shared__ float t[32][33];
    const int k0 = blockIdx.x * 32;
    const int c0 = blockIdx.y * 32;
    const int h  = c0 >> 6;
    const int ub = c0 & 63;
    const int tx = threadIdx.x & 31, ty = threadIdx.x >> 5;

    for (int kk = ty; kk < 32; kk += 8)
        t[kk][tx] = W[(size_t)h * FF * UU + (size_t)(k0 + kk) * UU + ub + tx];
    __syncthreads();
    for (int cc = ty; cc < 32; cc += 8) {
        float v = t[tx][cc];
        __nv_bfloat16 hi = __float2bfloat16(v);
        g_Whi[(size_t)(c0 + cc) * FF + k0 + tx] = hi;
        g_Wlo[(size_t)(c0 + cc) * FF + k0 + tx] = __float2bfloat16(v - __bfloat162float(hi));
    }
}

// ---------------- Kernel 1: bf16x3 GEMM + fused f_self/f_neigh ----------------
// 3-stage cp.async pipeline, ONE barrier per iteration.
#define KCHUNK   32
#define ROWB     80
#define A_BYTES  (128 * ROWB)
#define B_BYTES  (64 * ROWB)
#define STAGE_B  (2 * A_BYTES + 2 * B_BYTES)   // 30720
#define NSTAGE   3
#define GEMM_SMEM (NSTAGE * STAGE_B)           // 92160

__global__ __launch_bounds__(256)
void gat_gemm_mma(const float* __restrict__ a_self, const float* __restrict__ a_neigh)
{
    extern __shared__ __align__(16) char dyn[];
    __shared__ float sm_as[UU], sm_an[UU];
    __shared__ float sred_fs[128], sred_fn[128];

    const int tid  = threadIdx.x;
    const int lane = tid & 31, wid = tid >> 5;
    const int bm = blockIdx.x * 128;
    const int hb = blockIdx.y;
    const int bn = hb * 64;
    const int mw = (wid >> 1) * 32;
    const int nw = (wid & 1) * 32;

    if (tid < UU) {
        sm_as[tid] = a_self[hb * UU + tid];
        sm_an[tid] = a_neigh[hb * UU + tid];
    }

    const uint32_t sbase = smem_u32(dyn);

    float acc[2][4][4];
#pragma unroll
    for (int mi = 0; mi < 2; mi++)
#pragma unroll
        for (int nj = 0; nj < 4; nj++)
#pragma unroll
            for (int q = 0; q < 4; q++) acc[mi][nj][q] = 0.f;

    const int a_row0 = tid >> 2, a_seg = tid & 3;
    const int b_row  = tid >> 2, b_seg = tid & 3;
    const int a_r = (lane & 15);
    const int a_k = (lane >> 4) * 8;
    const int b_c = ((lane >> 4) << 3) + (lane & 7);
    const int b_k = ((lane >> 3) & 1) * 8;

    auto issue = [&](int t) {
        const int st = t % NSTAGE;
        const uint32_t pAh = sbase + st * STAGE_B;
        const uint32_t pAl = pAh + A_BYTES;
        const uint32_t pBh = pAl + A_BYTES;
        const uint32_t pBl = pBh + B_BYTES;
        const int kc = t * KCHUNK;
#pragma unroll
        for (int it = 0; it < 2; it++) {
            int row = a_row0 + it * 64;
            size_t go = (size_t)(bm + row) * FF + kc + a_seg * 8;
            uint32_t so = (uint32_t)(row * ROWB + a_seg * 16);
            cp16(pAh + so, g_Xhi + go);
            cp16(pAl + so, g_Xlo + go);
        }
        {
            size_t go = (size_t)(bn + b_row) * FF + kc + b_seg * 8;
            uint32_t so = (uint32_t)(b_row * ROWB + b_seg * 16);
            cp16(pBh + so, g_Whi + go);
            cp16(pBl + so, g_Wlo + go);
        }
        CP_COMMIT();
    };

    const int T = FF / KCHUNK;    // 16
    issue(0);
    issue(1);
    for (int t = 0; t < T; t++) {
        CP_WAIT1();               // stage t complete (<=1 group outstanding)
        __syncthreads();          // single barrier per iter

        const int st = t % NSTAGE;
        const uint32_t pAh = sbase + st * STAGE_B;
        const uint32_t pAl = pAh + A_BYTES;
        const uint32_t pBh = pAl + A_BYTES;
        const uint32_t pBl = pBh + B_BYTES;

#pragma unroll
        for (int ks = 0; ks < 2; ks++) {
            const int kk = ks * 16;
            uint32_t ah[2][4], al[2][4];
#pragma unroll
            for (int mi = 0; mi < 2; mi++) {
                uint32_t ao = (uint32_t)((mw + mi * 16 + a_r) * ROWB + (kk + a_k) * 2);
                ldsm_x4(ah[mi], pAh + ao);
                ldsm_x4(al[mi], pAl + ao);
            }
            uint32_t bh[4][2], bl[4][2];
#pragma unroll
            for (int bj = 0; bj < 2; bj++) {
                uint32_t bo = (uint32_t)((nw + bj * 16 + b_c) * ROWB + (kk + b_k) * 2);
                uint32_t r[4];
                ldsm_x4(r, pBh + bo);
                bh[bj * 2][0] = r[0]; bh[bj * 2][1] = r[1];
                bh[bj * 2 + 1][0] = r[2]; bh[bj * 2 + 1][1] = r[3];
                ldsm_x4(r, pBl + bo);
                bl[bj * 2][0] = r[0]; bl[bj * 2][1] = r[1];
                bl[bj * 2 + 1][0] = r[2]; bl[bj * 2 + 1][1] = r[3];
            }
#pragma unroll
            for (int mi = 0; mi < 2; mi++)
#pragma unroll
                for (int nj = 0; nj < 4; nj++) {
                    mma16816(acc[mi][nj], ah[mi], bh[nj]);
                    mma16816(acc[mi][nj], ah[mi], bl[nj]);
                    mma16816(acc[mi][nj], al[mi], bh[nj]);
                }
        }
        if (t + 2 < T) issue(t + 2);
    }

    // ---- epilogue: store hfeat (fp16) + fused f_self/f_neigh ----
    const int er = lane >> 2;
    const int ec = (lane & 3) * 2;
#pragma unroll
    for (int mi = 0; mi < 2; mi++) {
        const int row = bm + mw + mi * 16 + er;
#pragma unroll
        for (int nj = 0; nj < 4; nj++) {
            const int col = bn + nw + nj * 8 + ec;
            *reinterpret_cast<__half2*>(g_hfeat + (size_t)row * HU + col) =
                __floats2half2_rn(acc[mi][nj][0], acc[mi][nj][1]);
            *reinterpret_cast<__half2*>(g_hfeat + (size_t)(row + 8) * HU + col) =
                __floats2half2_rn(acc[mi][nj][2], acc[mi][nj][3]);
        }
    }

    float fsv[2][2], fnv[2][2];
#pragma unroll
    for (int mi = 0; mi < 2; mi++) {
        float fs0 = 0.f, fs1 = 0.f, fn0 = 0.f, fn1 = 0.f;
#pragma unroll
        for (int nj = 0; nj < 4; nj++) {
            const int c = nw + nj * 8 + ec;
            float as0 = sm_as[c], as1 = sm_as[c + 1];
            float an0 = sm_an[c], an1 = sm_an[c + 1];
            fs0 += acc[mi][nj][0] * as0 + acc[mi][nj][1] * as1;
            fs1 += acc[mi][nj][2] * as0 + acc[mi][nj][3] * as1;
            fn0 += acc[mi][nj][0] * an0 + acc[mi][nj][1] * an1;
            fn1 += acc[mi][nj][2] * an0 + acc[mi][nj][3] * an1;
        }
        fsv[mi][0] = fs0; fsv[mi][1] = fs1;
        fnv[mi][0] = fn0; fnv[mi][1] = fn1;
    }
#pragma unroll
    for (int mi = 0; mi < 2; mi++)
#pragma unroll
        for (int rh = 0; rh < 2; rh++) {
            fsv[mi][rh] += __shfl_xor_sync(0xFFFFFFFFu, fsv[mi][rh], 1);
            fsv[mi][rh] += __shfl_xor_sync(0xFFFFFFFFu, fsv[mi][rh], 2);
            fnv[mi][rh] += __shfl_xor_sync(0xFFFFFFFFu, fnv[mi][rh], 1);
            fnv[mi][rh] += __shfl_xor_sync(0xFFFFFFFFu, fnv[mi][rh], 2);
        }
    if (nw == 0 && (lane & 3) == 0) {
#pragma unroll
        for (int mi = 0; mi < 2; mi++) {
            sred_fs[mw + mi * 16 + er]     = fsv[mi][0];
            sred_fs[mw + mi * 16 + er + 8] = fsv[mi][1];
            sred_fn[mw + mi * 16 + er]     = fnv[mi][0];
            sred_fn[mw + mi * 16 + er + 8] = fnv[mi][1];
        }
    }
    __syncthreads();
    if (nw == 32 && (lane & 3) == 0) {
#pragma unroll
        for (int mi = 0; mi < 2; mi++)
#pragma unroll
            for (int rh = 0; rh < 2; rh++) {
                const int r = mw + mi * 16 + er + rh * 8;
                g_fs[(size_t)(bm + r) * HH + hb] = sred_fs[r] + fsv[mi][rh];
                g_fn[(size_t)(bm + r) * HH + hb] = sred_fn[r] + fnv[mi][rh];
            }
    }
}

// ---------------- Kernel 3: aggregation (fp16 gather, unroll-8 MLP) ----------------
__global__ __launch_bounds__(128)
void gat_aggregate(const float* __restrict__ A,
                   const float* __restrict__ bias,
                   float* __restrict__ out)
{
    const int i   = blockIdx.x;
    const int tid = threadIdx.x;            // 0..127
    const int lane = tid & 31, wid = tid >> 5;
    const int h   = tid >> 4;               // head (16 threads per head)
    const int sub = tid & 15;

    __shared__ int   sm_edges[EMAX];        // stores j<<9 (half-unit row offset)
    __shared__ float sm_w[HH][EMAX];
    __shared__ int   sm_psum[4];
    __shared__ float sm_fs[HH];

    if (tid < HH) sm_fs[tid] = g_fs[i * HH + tid];

    // ---- pass 1: count nonzeros in this thread's 32 columns ----
    const float4* Arow = reinterpret_cast<const float4*>(A + (size_t)i * NN);
    int cnt = 0;
#pragma unroll
    for (int q = 0; q < 8; q++) {
        float4 v = Arow[tid * 8 + q];
        cnt += (v.x != 0.f) + (v.y != 0.f) + (v.z != 0.f) + (v.w != 0.f);
    }
    int incl = cnt;
#pragma unroll
    for (int o = 1; o < 32; o <<= 1) {
        int nv = __shfl_up_sync(0xFFFFFFFFu, incl, o);
        if (lane >= o) incl += nv;
    }
    if (lane == 31) sm_psum[wid] = incl;
    __syncthreads();
    if (tid == 0) {
        int s = 0;
#pragma unroll
        for (int w = 0; w < 4; w++) { int v = sm_psum[w]; sm_psum[w] = s + v; s += v; }
    }
    __syncthreads();
    // ---- pass 2: rescan (L1-hot) and append ordered (clamped) ----
    {
        int base = (wid ? sm_psum[wid - 1] : 0) + incl - cnt;
        int col0 = tid * 32;
#pragma unroll
        for (int q = 0; q < 8; q++) {
            float4 v = Arow[tid * 8 + q];
            int c = col0 + q * 4;
            if (v.x != 0.f) { sm_edges[min(base, EMAX - 1)] = (c + 0) << 9; base++; }
            if (v.y != 0.f) { sm_edges[min(base, EMAX - 1)] = (c + 1) << 9; base++; }
            if (v.z != 0.f) { sm_edges[min(base, EMAX - 1)] = (c + 2) << 9; base++; }
            if (v.w != 0.f) { sm_edges[min(base, EMAX - 1)] = (c + 3) << 9; base++; }
        }
    }
    __syncthreads();
    const int E = min(sm_psum[3], EMAX);

    // ---- weight phase: all E edges, all 8 heads, one pass ----
    for (int e = tid; e < E; e += 128) {
        int j8 = sm_edges[e] >> 6;          // j*8
        float4 f0 = *reinterpret_cast<const float4*>(g_fn + j8);
        float4 f1 = *reinterpret_cast<const float4*>(g_fn + j8 + 4);
        float fn8[8] = {f0.x, f0.y, f0.z, f0.w, f1.x, f1.y, f1.z, f1.w};
#pragma unroll
        for (int hh = 0; hh < HH; hh++) {
            float x = sm_fs[hh] + fn8[hh];
            x = x > 0.f ? x : LRELU * x;
            sm_w[hh][e] = __expf(x);
        }
    }
    __syncthreads();

    // ---- den partials ----
    float den = 0.f;
    for (int e = sub; e < E; e += 16) den += sm_w[h][e];

    // ---- gather-FMA over fp16 rows, unroll 8 (MLP 8) ----
    const __half* hb = g_hfeat + tid * 4;   // thread's 4 columns
    float4 acc = make_float4(0.f, 0.f, 0.f, 0.f);
    int e = 0;
    for (; e + 8 <= E; e += 8) {
        int   o[8];
        float w[8];
        uint2 u[8];
#pragma unroll
        for (int q = 0; q < 8; q++) { o[q] = sm_edges[e + q]; w[q] = sm_w[h][e + q]; }
#pragma unroll
        for (int q = 0; q < 8; q++) u[q] = *reinterpret_cast<const uint2*>(hb + o[q]);
#pragma unroll
        for (int q = 0; q < 8; q++) {
            float2 pa = __half22float2(*reinterpret_cast<__half2*>(&u[q].x));
            float2 pb = __half22float2(*reinterpret_cast<__half2*>(&u[q].y));
            acc.x = fmaf(w[q], pa.x, acc.x); acc.y = fmaf(w[q], pa.y, acc.y);
            acc.z = fmaf(w[q], pb.x, acc.z); acc.w = fmaf(w[q], pb.y, acc.w);
        }
    }
    for (; e < E; e++) {
        int o0 = sm_edges[e];
        float w0 = sm_w[h][e];
        uint2 u0 = *reinterpret_cast<const uint2*>(hb + o0);
        float2 pa = __half22float2(*reinterpret_cast<__half2*>(&u0.x));
        float2 pb = __half22float2(*reinterpret_cast<__half2*>(&u0.y));
        acc.x = fmaf(w0, pa.x, acc.x); acc.y = fmaf(w0, pa.y, acc.y);
        acc.z = fmaf(w0, pb.x, acc.z); acc.w = fmaf(w0, pb.y, acc.w);
    }

    // segment-reduce den over the 16 lanes of this head
#pragma unroll
    for (int o = 8; o; o >>= 1) den += __shfl_xor_sync(0xFFFFFFFFu, den, o);
    const float rden = 1.f / den;

    float4 b4 = *reinterpret_cast<const float4*>(bias + tid * 4);
    float4 r;
    r.x = fmaf(acc.x, rden, b4.x); r.y = fmaf(acc.y, rden, b4.y);
    r.z = fmaf(acc.z, rden, b4.z); r.w = fmaf(acc.w, rden, b4.w);
    r.x = r.x > 0.f ? r.x : 0.f;
    r.y = r.y > 0.f ? r.y : 0.f;
    r.z = r.z > 0.f ? r.z : 0.f;
    r.w = r.w > 0.f ? r.w : 0.f;
    *reinterpret_cast<float4*>(out + (size_t)i * HU + tid * 4) = r;
}

// ---------------- launch ----------------
extern "C" void kernel_launch(void* const* d_in, const int* in_sizes, int n_in,
                              void* d_out, int out_size)
{
    const float* X       = (const float*)d_in[0];
    const float* A       = (const float*)d_in[2];
    const float* W       = (const float*)d_in[3];
    const float* a_self  = (const float*)d_in[4];
    const float* a_neigh = (const float*)d_in[5];
    const float* bias    = (const float*)d_in[6];
    float* out = (float*)d_out;

    cudaFuncSetAttribute(gat_gemm_mma, cudaFuncAttributeMaxDynamicSharedMemorySize, GEMM_SMEM);

    split_X_k<<<NN * FF / 4 / 256, 256>>>(X);
    split_W_k<<<dim3(FF / 32, HU / 32), 256>>>(W);
    gat_gemm_mma<<<dim3(NN / 128, HU / 64), 256, GEMM_SMEM>>>(a_self, a_neigh);
    gat_aggregate<<<NN, 128>>>(A, bias, out);
}

// round 11
// speedup vs baseline: 1.0270x; 1.0004x over previous
#include <cuda_runtime.h>
#include <cuda_bf16.h>
#include <cuda_fp16.h>
#include <cstdint>

#define NN   4096
#define FF   512
#define UU   64
#define HH   8
#define HU   (HH*UU)     // 512
#define LRELU 0.2f
#define EMAX 256         // max edges/row (mean 42, 33-sigma safe; writes clamped)

// ---------------- scratch ----------------
__device__ __half g_hfeat[NN * HU];           // [N, H*U] fp16, 4 MB (L2-resident)
__device__ float g_fs[NN * HH];
__device__ float g_fn[NN * HH];
__device__ uint32_t g_mask[NN * 128];         // adjacency bitmask, 2 MB
__device__ __nv_bfloat16 g_Xhi[NN * FF];
__device__ __nv_bfloat16 g_Xlo[NN * FF];
__device__ __nv_bfloat16 g_Whi[HU * FF];      // W^T [c][k]
__device__ __nv_bfloat16 g_Wlo[HU * FF];

// ---------------- helpers ----------------
__device__ __forceinline__ uint32_t smem_u32(const void* p) {
    uint32_t a;
    asm("{ .reg .u64 t; cvta.to.shared.u64 t, %1; cvt.u32.u64 %0, t; }" : "=r"(a) : "l"(p));
    return a;
}
__device__ __forceinline__ void ldsm_x4(uint32_t* r, uint32_t addr) {
    asm volatile("ldmatrix.sync.aligned.m8n8.x4.shared.b16 {%0,%1,%2,%3}, [%4];"
        : "=r"(r[0]), "=r"(r[1]), "=r"(r[2]), "=r"(r[3]) : "r"(addr));
}
__device__ __forceinline__ void mma16816(float* c, const uint32_t* a, const uint32_t* b) {
    asm volatile("mma.sync.aligned.m16n8k16.row.col.f32.bf16.bf16.f32 "
        "{%0,%1,%2,%3}, {%4,%5,%6,%7}, {%8,%9}, {%0,%1,%2,%3};"
        : "+f"(c[0]), "+f"(c[1]), "+f"(c[2]), "+f"(c[3])
        : "r"(a[0]), "r"(a[1]), "r"(a[2]), "r"(a[3]), "r"(b[0]), "r"(b[1]));
}
__device__ __forceinline__ void cp16(uint32_t dst, const void* src) {
    asm volatile("cp.async.cg.shared.global [%0], [%1], 16;" :: "r"(dst), "l"(src));
}
#define CP_COMMIT() asm volatile("cp.async.commit_group;" ::: "memory")
#define CP_WAIT1()  asm volatile("cp.async.wait_group 1;" ::: "memory")
#define CP_WAIT0()  asm volatile("cp.async.wait_group 0;" ::: "memory")

// ---------------- preprocess: split X into bf16 hi/lo ----------------
__global__ __launch_bounds__(256)
void split_X_k(const float* __restrict__ X)
{
    int idx = blockIdx.x * 256 + threadIdx.x;
    float4 v = reinterpret_cast<const float4*>(X)[idx];
    __nv_bfloat16 h0 = __float2bfloat16(v.x), h1 = __float2bfloat16(v.y);
    __nv_bfloat16 h2 = __float2bfloat16(v.z), h3 = __float2bfloat16(v.w);
    __nv_bfloat16 l0 = __float2bfloat16(v.x - __bfloat162float(h0));
    __nv_bfloat16 l1 = __float2bfloat16(v.y - __bfloat162float(h1));
    __nv_bfloat16 l2 = __float2bfloat16(v.z - __bfloat162float(h2));
    __nv_bfloat16 l3 = __float2bfloat16(v.w - __bfloat162float(h3));
    __nv_bfloat162* ph = reinterpret_cast<__nv_bfloat162*>(g_Xhi);
    __nv_bfloat162* pl = reinterpret_cast<__nv_bfloat162*>(g_Xlo);
    ph[idx * 2]     = __halves2bfloat162(h0, h1);
    ph[idx * 2 + 1] = __halves2bfloat162(h2, h3);
    pl[idx * 2]     = __halves2bfloat162(l0, l1);
    pl[idx * 2 + 1] = __halves2bfloat162(l2, l3);
}

// ---------------- preprocess: W [H,F,U] -> W^T bf16 hi/lo [c][k] ----------------
__global__ __launch_bounds__(256)
void split_W_k(const float* __restrict__ W)
{
    __shared__ float t[32][33];
    const int k0 = blockIdx.x * 32;
    const int c0 = blockIdx.y * 32;
    const int h  = c0 >> 6;
    const int ub = c0 & 63;
    const int tx = threadIdx.x & 31, ty = threadIdx.x >> 5;

    for (int kk = ty; kk < 32; kk += 8)
        t[kk][tx] = W[(size_t)h * FF * UU + (size_t)(k0 + kk) * UU + ub + tx];
    __syncthreads();
    for (int cc = ty; cc < 32; cc += 8) {
        float v = t[tx][cc];
        __nv_bfloat16 hi = __float2bfloat16(v);
        g_Whi[(size_t)(c0 + cc) * FF + k0 + tx] = hi;
        g_Wlo[(size_t)(c0 + cc) * FF + k0 + tx] = __float2bfloat16(v - __bfloat162float(hi));
    }
}

// ---------------- Kernel 0: A -> bitmask (pure streaming) ----------------
// thread owns 32 cols (8 float4 reads, MLP 8) -> one uint32
__global__ __launch_bounds__(256)
void build_mask(const float* __restrict__ A)
{
    int gid = blockIdx.x * 256 + threadIdx.x;      // 0 .. NN*128-1
    const float4* p = reinterpret_cast<const float4*>(A) + (size_t)gid * 8;
    uint32_t m = 0;
#pragma unroll
    for (int q = 0; q < 8; q++) {
        float4 v = p[q];
        m |= (uint32_t)(v.x != 0.f) << (q * 4);
        m |= (uint32_t)(v.y != 0.f) << (q * 4 + 1);
        m |= (uint32_t)(v.z != 0.f) << (q * 4 + 2);
        m |= (uint32_t)(v.w != 0.f) << (q * 4 + 3);
    }
    g_mask[gid] = m;
}

// ---------------- Kernel 1: bf16x3 GEMM + fused f_self/f_neigh ----------------
// 3-stage cp.async pipeline, ONE barrier per iteration.
#define KCHUNK   32
#define ROWB     80
#define A_BYTES  (128 * ROWB)
#define B_BYTES  (64 * ROWB)
#define STAGE_B  (2 * A_BYTES + 2 * B_BYTES)   // 30720
#define NSTAGE   3
#define GEMM_SMEM (NSTAGE * STAGE_B)           // 92160

__global__ __launch_bounds__(256)
void gat_gemm_mma(const float* __restrict__ a_self, const float* __restrict__ a_neigh)
{
    extern __shared__ __align__(16) char dyn[];
    __shared__ float sm_as[UU], sm_an[UU];
    __shared__ float sred_fs[128], sred_fn[128];

    const int tid  = threadIdx.x;
    const int lane = tid & 31, wid = tid >> 5;
    const int bm = blockIdx.x * 128;
    const int hb = blockIdx.y;
    const int bn = hb * 64;
    const int mw = (wid >> 1) * 32;
    const int nw = (wid & 1) * 32;

    if (tid < UU) {
        sm_as[tid] = a_self[hb * UU + tid];
        sm_an[tid] = a_neigh[hb * UU + tid];
    }

    const uint32_t sbase = smem_u32(dyn);

    float acc[2][4][4];
#pragma unroll
    for (int mi = 0; mi < 2; mi++)
#pragma unroll
        for (int nj = 0; nj < 4; nj++)
#pragma unroll
            for (int q = 0; q < 4; q++) acc[mi][nj][q] = 0.f;

    const int a_row0 = tid >> 2, a_seg = tid & 3;
    const int b_row  = tid >> 2, b_seg = tid & 3;
    const int a_r = (lane & 15);
    const int a_k = (lane >> 4) * 8;
    const int b_c = ((lane >> 4) << 3) + (lane & 7);
    const int b_k = ((lane >> 3) & 1) * 8;

    auto issue = [&](int t) {
        const int st = t % NSTAGE;
        const uint32_t pAh = sbase + st * STAGE_B;
        const uint32_t pAl = pAh + A_BYTES;
        const uint32_t pBh = pAl + A_BYTES;
        const uint32_t pBl = pBh + B_BYTES;
        const int kc = t * KCHUNK;
#pragma unroll
        for (int it = 0; it < 2; it++) {
            int row = a_row0 + it * 64;
            size_t go = (size_t)(bm + row) * FF + kc + a_seg * 8;
            uint32_t so = (uint32_t)(row * ROWB + a_seg * 16);
            cp16(pAh + so, g_Xhi + go);
            cp16(pAl + so, g_Xlo + go);
        }
        {
            size_t go = (size_t)(bn + b_row) * FF + kc + b_seg * 8;
            uint32_t so = (uint32_t)(b_row * ROWB + b_seg * 16);
            cp16(pBh + so, g_Whi + go);
            cp16(pBl + so, g_Wlo + go);
        }
        CP_COMMIT();
    };

    const int T = FF / KCHUNK;    // 16
    issue(0);
    issue(1);
    for (int t = 0; t < T; t++) {
        CP_WAIT1();
        __syncthreads();

        const int st = t % NSTAGE;
        const uint32_t pAh = sbase + st * STAGE_B;
        const uint32_t pAl = pAh + A_BYTES;
        const uint32_t pBh = pAl + A_BYTES;
        const uint32_t pBl = pBh + B_BYTES;

#pragma unroll
        for (int ks = 0; ks < 2; ks++) {
            const int kk = ks * 16;
            uint32_t ah[2][4], al[2][4];
#pragma unroll
            for (int mi = 0; mi < 2; mi++) {
                uint32_t ao = (uint32_t)((mw + mi * 16 + a_r) * ROWB + (kk + a_k) * 2);
                ldsm_x4(ah[mi], pAh + ao);
                ldsm_x4(al[mi], pAl + ao);
            }
            uint32_t bh[4][2], bl[4][2];
#pragma unroll
            for (int bj = 0; bj < 2; bj++) {
                uint32_t bo = (uint32_t)((nw + bj * 16 + b_c) * ROWB + (kk + b_k) * 2);
                uint32_t r[4];
                ldsm_x4(r, pBh + bo);
                bh[bj * 2][0] = r[0]; bh[bj * 2][1] = r[1];
                bh[bj * 2 + 1][0] = r[2]; bh[bj * 2 + 1][1] = r[3];
                ldsm_x4(r, pBl + bo);
                bl[bj * 2][0] = r[0]; bl[bj * 2][1] = r[1];
                bl[bj * 2 + 1][0] = r[2]; bl[bj * 2 + 1][1] = r[3];
            }
#pragma unroll
            for (int mi = 0; mi < 2; mi++)
#pragma unroll
                for (int nj = 0; nj < 4; nj++) {
                    mma16816(acc[mi][nj], ah[mi], bh[nj]);
                    mma16816(acc[mi][nj], ah[mi], bl[nj]);
                    mma16816(acc[mi][nj], al[mi], bh[nj]);
                }
        }
        if (t + 2 < T) issue(t + 2);
    }

    // ---- epilogue: store hfeat (fp16) + fused f_self/f_neigh ----
    const int er = lane >> 2;
    const int ec = (lane & 3) * 2;
#pragma unroll
    for (int mi = 0; mi < 2; mi++) {
        const int row = bm + mw + mi * 16 + er;
#pragma unroll
        for (int nj = 0; nj < 4; nj++) {
            const int col = bn + nw + nj * 8 + ec;
            *reinterpret_cast<__half2*>(g_hfeat + (size_t)row * HU + col) =
                __floats2half2_rn(acc[mi][nj][0], acc[mi][nj][1]);
            *reinterpret_cast<__half2*>(g_hfeat + (size_t)(row + 8) * HU + col) =
                __floats2half2_rn(acc[mi][nj][2], acc[mi][nj][3]);
        }
    }

    float fsv[2][2], fnv[2][2];
#pragma unroll
    for (int mi = 0; mi < 2; mi++) {
        float fs0 = 0.f, fs1 = 0.f, fn0 = 0.f, fn1 = 0.f;
#pragma unroll
        for (int nj = 0; nj < 4; nj++) {
            const int c = nw + nj * 8 + ec;
            float as0 = sm_as[c], as1 = sm_as[c + 1];
            float an0 = sm_an[c], an1 = sm_an[c + 1];
            fs0 += acc[mi][nj][0] * as0 + acc[mi][nj][1] * as1;
            fs1 += acc[mi][nj][2] * as0 + acc[mi][nj][3] * as1;
            fn0 += acc[mi][nj][0] * an0 + acc[mi][nj][1] * an1;
            fn1 += acc[mi][nj][2] * an0 + acc[mi][nj][3] * an1;
        }
        fsv[mi][0] = fs0; fsv[mi][1] = fs1;
        fnv[mi][0] = fn0; fnv[mi][1] = fn1;
    }
#pragma unroll
    for (int mi = 0; mi < 2; mi++)
#pragma unroll
        for (int rh = 0; rh < 2; rh++) {
            fsv[mi][rh] += __shfl_xor_sync(0xFFFFFFFFu, fsv[mi][rh], 1);
            fsv[mi][rh] += __shfl_xor_sync(0xFFFFFFFFu, fsv[mi][rh], 2);
            fnv[mi][rh] += __shfl_xor_sync(0xFFFFFFFFu, fnv[mi][rh], 1);
            fnv[mi][rh] += __shfl_xor_sync(0xFFFFFFFFu, fnv[mi][rh], 2);
        }
    if (nw == 0 && (lane & 3) == 0) {
#pragma unroll
        for (int mi = 0; mi < 2; mi++) {
            sred_fs[mw + mi * 16 + er]     = fsv[mi][0];
            sred_fs[mw + mi * 16 + er + 8] = fsv[mi][1];
            sred_fn[mw + mi * 16 + er]     = fnv[mi][0];
            sred_fn[mw + mi * 16 + er + 8] = fnv[mi][1];
        }
    }
    __syncthreads();
    if (nw == 32 && (lane & 3) == 0) {
#pragma unroll
        for (int mi = 0; mi < 2; mi++)
#pragma unroll
            for (int rh = 0; rh < 2; rh++) {
                const int r = mw + mi * 16 + er + rh * 8;
                g_fs[(size_t)(bm + r) * HH + hb] = sred_fs[r] + fsv[mi][rh];
                g_fn[(size_t)(bm + r) * HH + hb] = sred_fn[r] + fnv[mi][rh];
            }
    }
}

// ---------------- Kernel 3: aggregation (bitmask scan + fp16 gather) ----------------
__global__ __launch_bounds__(128)
void gat_aggregate(const float* __restrict__ bias,
                   float* __restrict__ out)
{
    const int i   = blockIdx.x;
    const int tid = threadIdx.x;            // 0..127
    const int lane = tid & 31, wid = tid >> 5;
    const int h   = tid >> 4;               // head (16 threads per head)
    const int sub = tid & 15;

    __shared__ int   sm_edges[EMAX];        // stores j<<9 (half-unit row offset)
    __shared__ float sm_w[HH][EMAX];
    __shared__ int   sm_psum[4];
    __shared__ float sm_fs[HH];

    if (tid < HH) sm_fs[tid] = g_fs[i * HH + tid];

    // ---- scan: 512 B bitmask per row; thread owns 32 cols ----
    uint32_t m = g_mask[i * 128 + tid];
    int cnt = __popc(m);
    int incl = cnt;
#pragma unroll
    for (int o = 1; o < 32; o <<= 1) {
        int nv = __shfl_up_sync(0xFFFFFFFFu, incl, o);
        if (lane >= o) incl += nv;
    }
    if (lane == 31) sm_psum[wid] = incl;
    __syncthreads();
    if (tid == 0) {
        int s = 0;
#pragma unroll
        for (int w = 0; w < 4; w++) { int v = sm_psum[w]; sm_psum[w] = s + v; s += v; }
    }
    __syncthreads();
    {
        int base = (wid ? sm_psum[wid - 1] : 0) + incl - cnt;
        int c0 = tid * 32;
        uint32_t mm = m;
        while (mm) {
            int b = __ffs(mm) - 1;
            mm &= mm - 1;
            sm_edges[min(base, EMAX - 1)] = (c0 + b) << 9;
            base++;
        }
    }
    __syncthreads();
    const int E = min(sm_psum[3], EMAX);

    // ---- weight phase: all E edges, all 8 heads, one pass ----
    for (int e = tid; e < E; e += 128) {
        int j8 = sm_edges[e] >> 6;          // j*8
        float4 f0 = *reinterpret_cast<const float4*>(g_fn + j8);
        float4 f1 = *reinterpret_cast<const float4*>(g_fn + j8 + 4);
        float fn8[8] = {f0.x, f0.y, f0.z, f0.w, f1.x, f1.y, f1.z, f1.w};
#pragma unroll
        for (int hh = 0; hh < HH; hh++) {
            float x = sm_fs[hh] + fn8[hh];
            x = x > 0.f ? x : LRELU * x;
            sm_w[hh][e] = __expf(x);
        }
    }
    __syncthreads();

    // ---- den partials ----
    float den = 0.f;
    for (int e = sub; e < E; e += 16) den += sm_w[h][e];

    // ---- gather-FMA over fp16 rows, unroll 8 ----
    const __half* hb = g_hfeat + tid * 4;   // thread's 4 columns
    float4 acc = make_float4(0.f, 0.f, 0.f, 0.f);
    int e = 0;
    for (; e + 8 <= E; e += 8) {
        int   o[8];
        float w[8];
        uint2 u[8];
#pragma unroll
        for (int q = 0; q < 8; q++) { o[q] = sm_edges[e + q]; w[q] = sm_w[h][e + q]; }
#pragma unroll
        for (int q = 0; q < 8; q++) u[q] = *reinterpret_cast<const uint2*>(hb + o[q]);
#pragma unroll
        for (int q = 0; q < 8; q++) {
            float2 pa = __half22float2(*reinterpret_cast<__half2*>(&u[q].x));
            float2 pb = __half22float2(*reinterpret_cast<__half2*>(&u[q].y));
            acc.x = fmaf(w[q], pa.x, acc.x); acc.y = fmaf(w[q], pa.y, acc.y);
            acc.z = fmaf(w[q], pb.x, acc.z); acc.w = fmaf(w[q], pb.y, acc.w);
        }
    }
    for (; e < E; e++) {
        int o0 = sm_edges[e];
        float w0 = sm_w[h][e];
        uint2 u0 = *reinterpret_cast<const uint2*>(hb + o0);
        float2 pa = __half22float2(*reinterpret_cast<__half2*>(&u0.x));
        float2 pb = __half22float2(*reinterpret_cast<__half2*>(&u0.y));
        acc.x = fmaf(w0, pa.x, acc.x); acc.y = fmaf(w0, pa.y, acc.y);
        acc.z = fmaf(w0, pb.x, acc.z); acc.w = fmaf(w0, pb.y, acc.w);
    }

    // segment-reduce den over the 16 lanes of this head
#pragma unroll
    for (int o = 8; o; o >>= 1) den += __shfl_xor_sync(0xFFFFFFFFu, den, o);
    const float rden = 1.f / den;

    float4 b4 = *reinterpret_cast<const float4*>(bias + tid * 4);
    float4 r;
    r.x = fmaf(acc.x, rden, b4.x); r.y = fmaf(acc.y, rden, b4.y);
    r.z = fmaf(acc.z, rden, b4.z); r.w = fmaf(acc.w, rden, b4.w);
    r.x = r.x > 0.f ? r.x : 0.f;
    r.y = r.y > 0.f ? r.y : 0.f;
    r.z = r.z > 0.f ? r.z : 0.f;
    r.w = r.w > 0.f ? r.w : 0.f;
    *reinterpret_cast<float4*>(out + (size_t)i * HU + tid * 4) = r;
}

// ---------------- launch ----------------
extern "C" void kernel_launch(void* const* d_in, const int* in_sizes, int n_in,
                              void* d_out, int out_size)
{
    const float* X       = (const float*)d_in[0];
    const float* A       = (const float*)d_in[2];
    const float* W       = (const float*)d_in[3];
    const float* a_self  = (const float*)d_in[4];
    const float* a_neigh = (const float*)d_in[5];
    const float* bias    = (const float*)d_in[6];
    float* out = (float*)d_out;

    cudaFuncSetAttribute(gat_gemm_mma, cudaFuncAttributeMaxDynamicSharedMemorySize, GEMM_SMEM);

    build_mask<<<NN * 128 / 256, 256>>>(A);
    split_X_k<<<NN * FF / 4 / 256, 256>>>(X);
    split_W_k<<<dim3(FF / 32, HU / 32), 256>>>(W);
    gat_gemm_mma<<<dim3(NN / 128, HU / 64), 256, GEMM_SMEM>>>(a_self, a_neigh);
    gat_aggregate<<<NN, 128>>>(bias, out);
}